// round 1
// baseline (speedup 1.0000x reference)
#include <cuda_runtime.h>
#include <cuda_bf16.h>
#include <cstdint>

#define BB 64
#define HH 2048
#define KKN 256
#define MM (KKN*BB)          // 16384 rows
#define CEPS 1e-8f

// ---------------- scratch (static device globals; no allocation) -------------
__device__ __align__(16) float g_q[BB*HH];
__device__ __align__(16) float g_u[BB*HH];
__device__ float g_qn[BB];
__device__ float g_qdotb[BB];
__device__ float g_norm2[MM];
__device__ float g_dots[MM];
__device__ float g_attn[MM];
__device__ __align__(16) __nv_bfloat16 g_Wbf[HH*HH];
__device__ __align__(16) __nv_bfloat16 g_KBbf[(size_t)MM*HH];

// ---------------- small PTX helpers ------------------------------------------
__device__ __forceinline__ uint32_t swz128(uint32_t off){ return off ^ ((off>>3)&0x70u); }

__device__ __forceinline__ void cp16(uint32_t saddr, const void* gaddr){
  asm volatile("cp.async.cg.shared.global [%0], [%1], 16;\n" :: "r"(saddr), "l"(gaddr));
}
__device__ __forceinline__ void cp_commit(){ asm volatile("cp.async.commit_group;\n"); }
template<int N> __device__ __forceinline__ void cp_wait(){ asm volatile("cp.async.wait_group %0;\n" :: "n"(N)); }

__device__ __forceinline__ void ldmx4(uint32_t* r, uint32_t a){
  asm volatile("ldmatrix.sync.aligned.m8n8.x4.shared.b16 {%0,%1,%2,%3}, [%4];\n"
               : "=r"(r[0]), "=r"(r[1]), "=r"(r[2]), "=r"(r[3]) : "r"(a));
}
__device__ __forceinline__ void ldmx2(uint32_t* r, uint32_t a){
  asm volatile("ldmatrix.sync.aligned.m8n8.x2.shared.b16 {%0,%1}, [%2];\n"
               : "=r"(r[0]), "=r"(r[1]) : "r"(a));
}
__device__ __forceinline__ void mma16816(float* d, const uint32_t* a, const uint32_t* b){
  asm volatile("mma.sync.aligned.m16n8k16.row.col.f32.bf16.bf16.f32 "
               "{%0,%1,%2,%3}, {%4,%5,%6,%7}, {%8,%9}, {%0,%1,%2,%3};\n"
               : "+f"(d[0]), "+f"(d[1]), "+f"(d[2]), "+f"(d[3])
               : "r"(a[0]), "r"(a[1]), "r"(a[2]), "r"(a[3]), "r"(b[0]), "r"(b[1]));
}

// ---------------- q = x @ W^T + b  (tiled fp32, all 64 b x 64-o tile) --------
__global__ void __launch_bounds__(256) kq(const float* __restrict__ x,
                                          const float* __restrict__ W,
                                          const float* __restrict__ bias){
  __shared__ float xs[64][20];
  __shared__ float ws[64][20];
  int t = threadIdx.x;
  int ot = blockIdx.x * 64;
  int b0 = (t >> 4) * 4, o0 = (t & 15) * 4;
  float acc[4][4] = {};
  for (int h0 = 0; h0 < HH; h0 += 16){
    __syncthreads();
    #pragma unroll
    for (int i = 0; i < 4; i++){
      int id = t + i*256, r = id >> 4, c = id & 15;
      xs[r][c] = x[r*HH + h0 + c];
      ws[r][c] = W[(ot + r)*HH + h0 + c];
    }
    __syncthreads();
    #pragma unroll
    for (int k4 = 0; k4 < 4; k4++){
      float4 xa[4], wa[4];
      #pragma unroll
      for (int i = 0; i < 4; i++){
        xa[i] = *(const float4*)&xs[b0+i][k4*4];
        wa[i] = *(const float4*)&ws[o0+i][k4*4];
      }
      #pragma unroll
      for (int i = 0; i < 4; i++)
        #pragma unroll
        for (int j = 0; j < 4; j++)
          acc[i][j] += xa[i].x*wa[j].x + xa[i].y*wa[j].y + xa[i].z*wa[j].z + xa[i].w*wa[j].w;
    }
  }
  #pragma unroll
  for (int i = 0; i < 4; i++)
    #pragma unroll
    for (int j = 0; j < 4; j++)
      g_q[(b0+i)*HH + ot + o0 + j] = acc[i][j] + bias[ot + o0 + j];
}

// ---------------- u = q @ W  (u_b = W^T q_b) ---------------------------------
__global__ void __launch_bounds__(256) ku(const float* __restrict__ W){
  __shared__ float qs[64][17];
  __shared__ float ws[16][68];
  int t = threadIdx.x;
  int ht = blockIdx.x * 64;
  int b0 = (t >> 4) * 4, h0 = (t & 15) * 4;
  float acc[4][4] = {};
  for (int oc = 0; oc < HH; oc += 16){
    __syncthreads();
    #pragma unroll
    for (int i = 0; i < 4; i++){
      int id = t + i*256, r = id >> 4, c = id & 15;
      qs[r][c] = g_q[r*HH + oc + c];
    }
    #pragma unroll
    for (int i = 0; i < 4; i++){
      int id = t + i*256, r = id >> 6, c = id & 63;
      ws[r][c] = W[(oc + r)*HH + ht + c];
    }
    __syncthreads();
    #pragma unroll
    for (int oo = 0; oo < 16; oo++){
      float4 wv = *(const float4*)&ws[oo][h0];
      #pragma unroll
      for (int i = 0; i < 4; i++){
        float qv = qs[b0+i][oo];
        acc[i][0] += qv*wv.x; acc[i][1] += qv*wv.y;
        acc[i][2] += qv*wv.z; acc[i][3] += qv*wv.w;
      }
    }
  }
  #pragma unroll
  for (int i = 0; i < 4; i++)
    #pragma unroll
    for (int j = 0; j < 4; j++)
      g_u[(b0+i)*HH + ht + h0 + j] = acc[i][j];
}

// ---------------- per-b stats: ||q_b||, q_b . bias ---------------------------
__global__ void __launch_bounds__(256) kqstats(const float* __restrict__ bias){
  int b = blockIdx.x, t = threadIdx.x, lane = t & 31, warp = t >> 5;
  const float* qr = g_q + b*HH;
  float s2 = 0.f, sb = 0.f;
  for (int h = t; h < HH; h += 256){ float v = qr[h]; s2 += v*v; sb += v*bias[h]; }
  #pragma unroll
  for (int o = 16; o; o >>= 1){
    s2 += __shfl_xor_sync(0xffffffffu, s2, o);
    sb += __shfl_xor_sync(0xffffffffu, sb, o);
  }
  __shared__ float r2[8], rb[8];
  if (lane == 0){ r2[warp] = s2; rb[warp] = sb; }
  __syncthreads();
  if (t == 0){
    float a = 0.f, c = 0.f;
    #pragma unroll
    for (int i = 0; i < 8; i++){ a += r2[i]; c += rb[i]; }
    g_qn[b] = fmaxf(sqrtf(a), CEPS);
    g_qdotb[b] = c;
  }
}

// ---------------- W fp32 -> bf16 ---------------------------------------------
__global__ void __launch_bounds__(256) kconvW(const float* __restrict__ W){
  size_t base = ((size_t)blockIdx.x*256 + threadIdx.x) * 8;
  float4 a = *(const float4*)(W + base);
  float4 c = *(const float4*)(W + base + 4);
  __nv_bfloat16 o[8];
  o[0]=__float2bfloat16(a.x); o[1]=__float2bfloat16(a.y);
  o[2]=__float2bfloat16(a.z); o[3]=__float2bfloat16(a.w);
  o[4]=__float2bfloat16(c.x); o[5]=__float2bfloat16(c.y);
  o[6]=__float2bfloat16(c.z); o[7]=__float2bfloat16(c.w);
  *(uint4*)(g_Wbf + base) = *(uint4*)o;
}

// --------- dots[m] = u_b . kb_m + q_b.bias ; convert KB -> bf16 ; zero norm2 -
__global__ void __launch_bounds__(256) kdots(const float* __restrict__ KB){
  int m = blockIdx.x, t = threadIdx.x, lane = t & 31, warp = t >> 5;
  int b = m & (BB-1);
  const float* row = KB + (size_t)m*HH;
  const float* ur  = g_u + b*HH;
  int h = t*8;
  float4 a  = *(const float4*)(row + h);
  float4 a2 = *(const float4*)(row + h + 4);
  float4 u1 = *(const float4*)(ur + h);
  float4 u2 = *(const float4*)(ur + h + 4);
  float d = a.x*u1.x + a.y*u1.y + a.z*u1.z + a.w*u1.w
          + a2.x*u2.x + a2.y*u2.y + a2.z*u2.z + a2.w*u2.w;
  __nv_bfloat16 o[8];
  o[0]=__float2bfloat16(a.x);  o[1]=__float2bfloat16(a.y);
  o[2]=__float2bfloat16(a.z);  o[3]=__float2bfloat16(a.w);
  o[4]=__float2bfloat16(a2.x); o[5]=__float2bfloat16(a2.y);
  o[6]=__float2bfloat16(a2.z); o[7]=__float2bfloat16(a2.w);
  *(uint4*)(g_KBbf + (size_t)m*HH + h) = *(uint4*)o;
  #pragma unroll
  for (int s = 16; s; s >>= 1) d += __shfl_xor_sync(0xffffffffu, d, s);
  __shared__ float rs[8];
  if (lane == 0) rs[warp] = d;
  __syncthreads();
  if (t == 0){
    float s = 0.f;
    #pragma unroll
    for (int i = 0; i < 8; i++) s += rs[i];
    g_dots[m]  = s + g_qdotb[b];
    g_norm2[m] = 0.f;
  }
}

// ---------------- norm2[m] = || W @ kb_m ||^2  (bf16 HMMA, fused epilogue) ---
// C = KBbf[16384 x 2048] @ Wbf^T[2048 x 2048]; only row-wise sum C^2 survives.
__global__ void __launch_bounds__(256) kgemm_norm(){
  extern __shared__ char dsm[];
  __nv_bfloat16* sA = (__nv_bfloat16*)dsm;             // [2][128*64]
  __nv_bfloat16* sB = (__nv_bfloat16*)(dsm + 32768);   // [2][128*64]
  __shared__ float rowsum[128];
  const int t = threadIdx.x, lane = t & 31, warp = t >> 5;
  const int m0 = blockIdx.y * 128, n0 = blockIdx.x * 128;
  const int wm = (warp >> 2) * 64, wn = (warp & 3) * 32;
  if (t < 128) rowsum[t] = 0.f;

  float acc[4][4][4];
  #pragma unroll
  for (int i = 0; i < 4; i++)
    #pragma unroll
    for (int j = 0; j < 4; j++)
      #pragma unroll
      for (int c = 0; c < 4; c++) acc[i][j][c] = 0.f;

  uint32_t sAu = (uint32_t)__cvta_generic_to_shared(sA);
  uint32_t sBu = (uint32_t)__cvta_generic_to_shared(sB);

  uint32_t soff[4];
  const __nv_bfloat16 *gA[4], *gB[4];
  #pragma unroll
  for (int i = 0; i < 4; i++){
    int id = t + i*256, r = id >> 3, c = id & 7;
    soff[i] = swz128((uint32_t)(r*128 + c*16));
    gA[i] = g_KBbf + (size_t)(m0 + r)*HH + c*8;
    gB[i] = g_Wbf  + (size_t)(n0 + r)*HH + c*8;
  }

  auto issue = [&](int stage, int kc){
    uint32_t sa = sAu + stage*16384, sb = sBu + stage*16384;
    #pragma unroll
    for (int i = 0; i < 4; i++){
      cp16(sa + soff[i], gA[i] + kc);
      cp16(sb + soff[i], gB[i] + kc);
    }
    cp_commit();
  };

  issue(0, 0);
  const int NIT = HH/64;
  for (int it = 0; it < NIT; ++it){
    if (it + 1 < NIT){ issue((it+1)&1, (it+1)*64); cp_wait<1>(); }
    else              cp_wait<0>();
    __syncthreads();
    uint32_t sa = sAu + (it&1)*16384, sb = sBu + (it&1)*16384;
    #pragma unroll
    for (int ks = 0; ks < 4; ks++){
      uint32_t af[4][4], bf[4][2];
      #pragma unroll
      for (int mt = 0; mt < 4; mt++){
        int rr = wm + mt*16 + ((lane>>3)&1)*8 + (lane&7);
        int bc = ks*32 + (lane>>4)*16;
        ldmx4(af[mt], sa + swz128((uint32_t)(rr*128 + bc)));
      }
      #pragma unroll
      for (int nt = 0; nt < 4; nt++){
        int rr = wn + nt*8 + (lane&7);
        int bc = ks*32 + ((lane>>3)&1)*16;
        ldmx2(bf[nt], sb + swz128((uint32_t)(rr*128 + bc)));
      }
      #pragma unroll
      for (int mt = 0; mt < 4; mt++)
        #pragma unroll
        for (int nt = 0; nt < 4; nt++)
          mma16816(acc[mt][nt], af[mt], bf[nt]);
    }
    __syncthreads();
  }

  // epilogue: rows gid / gid+8 of each 16-row m-tile; reduce squares over n
  const int gid = lane >> 2, tig = lane & 3;
  #pragma unroll
  for (int mt = 0; mt < 4; mt++){
    float s0 = 0.f, s1 = 0.f;
    #pragma unroll
    for (int nt = 0; nt < 4; nt++){
      s0 += acc[mt][nt][0]*acc[mt][nt][0] + acc[mt][nt][1]*acc[mt][nt][1];
      s1 += acc[mt][nt][2]*acc[mt][nt][2] + acc[mt][nt][3]*acc[mt][nt][3];
    }
    s0 += __shfl_xor_sync(0xffffffffu, s0, 1);
    s0 += __shfl_xor_sync(0xffffffffu, s0, 2);
    s1 += __shfl_xor_sync(0xffffffffu, s1, 1);
    s1 += __shfl_xor_sync(0xffffffffu, s1, 2);
    if (tig == 0){
      atomicAdd(&rowsum[wm + mt*16 + gid],     s0);
      atomicAdd(&rowsum[wm + mt*16 + 8 + gid], s1);
    }
  }
  __syncthreads();
  if (t < 128) atomicAdd(&g_norm2[m0 + t], rowsum[t]);
}

// ---------------- scores + softmax over K ------------------------------------
__global__ void __launch_bounds__(256) ksoftmax(){
  int b = blockIdx.x, t = threadIdx.x, lane = t & 31, warp = t >> 5;
  int m = t*BB + b;
  float kn = fmaxf(sqrtf(g_norm2[m]), CEPS);
  float sc = g_dots[m] / (g_qn[b] * kn);
  __shared__ float sred[8];
  float v = sc;
  #pragma unroll
  for (int o = 16; o; o >>= 1) v = fmaxf(v, __shfl_xor_sync(0xffffffffu, v, o));
  if (lane == 0) sred[warp] = v;
  __syncthreads();
  float mx = sred[0];
  #pragma unroll
  for (int i = 1; i < 8; i++) mx = fmaxf(mx, sred[i]);
  float e = expf(sc - mx);
  float s = e;
  #pragma unroll
  for (int o = 16; o; o >>= 1) s += __shfl_xor_sync(0xffffffffu, s, o);
  __syncthreads();
  if (lane == 0) sred[warp] = s;
  __syncthreads();
  float tot = 0.f;
  #pragma unroll
  for (int i = 0; i < 8; i++) tot += sred[i];
  g_attn[m] = e / tot;
}

// ---------------- out = x + sum_k attn[k,b] * KB[k,b,:]  (fp32 KB) -----------
__global__ void __launch_bounds__(256) kout(const float* __restrict__ x,
                                            const float* __restrict__ KB,
                                            float* __restrict__ out){
  int b = blockIdx.y;
  int h = blockIdx.x*256 + threadIdx.x;
  __shared__ float at[KKN];
  at[threadIdx.x] = g_attn[threadIdx.x*BB + b];
  __syncthreads();
  float a0 = x[b*HH + h], a1 = 0.f, a2 = 0.f, a3 = 0.f;
  const float* p = KB + (size_t)b*HH + h;
  #pragma unroll 4
  for (int k = 0; k < KKN; k += 4){
    a0 += at[k]   * p[(size_t)(k  )*BB*HH];
    a1 += at[k+1] * p[(size_t)(k+1)*BB*HH];
    a2 += at[k+2] * p[(size_t)(k+2)*BB*HH];
    a3 += at[k+3] * p[(size_t)(k+3)*BB*HH];
  }
  out[b*HH + h] = a0 + a1 + a2 + a3;
}

// ---------------- launch ------------------------------------------------------
extern "C" void kernel_launch(void* const* d_in, const int* in_sizes, int n_in,
                              void* d_out, int out_size){
  const float* x    = (const float*)d_in[0];   // [64,2048]
  const float* KB   = (const float*)d_in[1];   // [256,64,2048]
  const float* W    = (const float*)d_in[2];   // [2048,2048]
  const float* bias = (const float*)d_in[3];   // [2048]
  float* out = (float*)d_out;

  cudaFuncSetAttribute(kgemm_norm, cudaFuncAttributeMaxDynamicSharedMemorySize, 65536);

  kq<<<32, 256>>>(x, W, bias);
  kqstats<<<64, 256>>>(bias);
  ku<<<32, 256>>>(W);
  kconvW<<<(HH*HH/8)/256, 256>>>(W);
  kdots<<<MM, 256>>>(KB);
  kgemm_norm<<<dim3(16, 128), 256, 65536>>>();
  ksoftmax<<<64, 256>>>();
  kout<<<dim3(HH/256, BB), 256>>>(x, KB, out);
}